// round 5
// baseline (speedup 1.0000x reference)
#include <cuda_runtime.h>
#include <math.h>
#include <stdint.h>

#define NB 16384      // batch rows
#define ND 1024       // feature dim
#define NC 65         // centroids incl. extra
#define EPSV 1e-8f
#define SPLITK 32
#define KCHUNK (NB / SPLITK)   // 512
#define NLOSSBLK (NB / 8)      // 2048 loss blocks (8 warps/block, warp per row)

// ---------------- scratch (static device globals; no allocation) ----------------
__device__ unsigned long long g_mask[NB];
__device__ int    g_counts[64];
__device__ int    g_nzero;
__device__ int    g_odd;                 // label-width detection: 1 => int32 layout
__device__ int    g_zrows[NB];
__device__ float  g_part[SPLITK][64 * ND];   // split-K partials (deterministic)
__device__ float  g_asum[NC * ND];
__device__ float  g_anc[NC * ND];            // anchors pre-divided by clamped norm
__device__ float  g_invxn[NB];
__device__ float  g_dots[(size_t)NB * NC];
__device__ double g_lpart[NLOSSBLK];         // deterministic per-block loss partials

// ---------------- init ----------------
__global__ void kInit() {
    int idx = blockIdx.x * blockDim.x + threadIdx.x;
    if (idx < NC * ND) g_asum[idx] = 0.0f;
    if (idx < 64)      g_counts[idx] = 0;
    if (idx == 0) { g_nzero = 0; g_odd = 0; }
}

// ---------------- label width detection ----------------
// If the buffer is true little-endian int64 with 0/1 values, every odd int32
// word is zero. Scan NB*64 int32 words — in-bounds for both layouts.
__global__ void kDetect(const int* lab32) {
    int found = 0;
    for (int idx = blockIdx.x * blockDim.x + threadIdx.x; idx < (NB * 64 / 2);
         idx += gridDim.x * blockDim.x) {
        if (lab32[2 * idx + 1] != 0) found = 1;
    }
    if (__syncthreads_or(found)) {
        if (threadIdx.x == 0) atomicOr(&g_odd, 1);
    }
}

// ---------------- masks + counts (warp per row) ----------------
__global__ __launch_bounds__(256) void kMask(const void* label) {
    __shared__ int s_cnt[64];
    if (threadIdx.x < 64) s_cnt[threadIdx.x] = 0;
    __syncthreads();

    int row  = (blockIdx.x * blockDim.x + threadIdx.x) >> 5;
    int lane = threadIdx.x & 31;
    bool is64 = (g_odd == 0);

    long long v0, v1;
    if (is64) {
        const long long* p = (const long long*)label;
        v0 = p[(size_t)row * 64 + lane];
        v1 = p[(size_t)row * 64 + 32 + lane];
    } else {
        const int* p = (const int*)label;
        v0 = p[(size_t)row * 64 + lane];
        v1 = p[(size_t)row * 64 + 32 + lane];
    }
    unsigned lo = __ballot_sync(0xffffffffu, v0 != 0);
    unsigned hi = __ballot_sync(0xffffffffu, v1 != 0);
    unsigned long long m = (unsigned long long)lo | ((unsigned long long)hi << 32);

    if (lane == 0) {
        g_mask[row] = m;
        if (m == 0ULL) {
            int p = atomicAdd(&g_nzero, 1);
            g_zrows[p] = row;
        }
    }
    if ((lo >> lane) & 1u) atomicAdd(&s_cnt[lane], 1);
    if ((hi >> lane) & 1u) atomicAdd(&s_cnt[lane + 32], 1);
    __syncthreads();
    if (threadIdx.x < 64) atomicAdd(&g_counts[threadIdx.x], s_cnt[threadIdx.x]);
}

// ---------------- GEMM1: part[ks] = labT(64 x Kchunk) @ x(Kchunk x 128cols) --------
#define KT1 32
__global__ __launch_bounds__(256) void kGemm1(const float* __restrict__ x) {
    int bx  = blockIdx.x;          // 0..7   column tile (128 cols)
    int ks  = blockIdx.y;          // 0..31  K slice
    int tid = threadIdx.x;

    __shared__ float s_a[KT1][64];     // lab bits as float, [k][m]
    __shared__ float s_b[KT1][128];    // x tile, [k][n]

    float acc[8][4];
#pragma unroll
    for (int i = 0; i < 8; i++)
#pragma unroll
        for (int j = 0; j < 4; j++) acc[i][j] = 0.0f;

    int m0 = (tid >> 5) * 8;       // 0..56
    int n0 = (tid & 31) * 4;       // 0..124
    int kbase = ks * KCHUNK;

    for (int t = 0; t < KCHUNK; t += KT1) {
        int k0 = kbase + t;
        __syncthreads();
        // x tile: 32 rows x 128 cols = 1024 float4, 4 per thread
#pragma unroll
        for (int p = 0; p < 4; p++) {
            int idx = tid + p * 256;
            int kr = idx >> 5;
            int nc = (idx & 31) << 2;
            float4 v = *(const float4*)&x[(size_t)(k0 + kr) * ND + bx * 128 + nc];
            *(float4*)&s_b[kr][nc] = v;
        }
        // lab tile from masks: 32 x 64 entries, 8 per thread
#pragma unroll
        for (int q = 0; q < 8; q++) {
            int idx = tid + q * 256;
            int kr = idx >> 6;
            int mm = idx & 63;
            s_a[kr][mm] = (float)((g_mask[k0 + kr] >> mm) & 1ULL);
        }
        __syncthreads();
#pragma unroll
        for (int k = 0; k < KT1; k++) {
            float4 t0 = *(const float4*)&s_a[k][m0];
            float4 t1 = *(const float4*)&s_a[k][m0 + 4];
            float4 t2 = *(const float4*)&s_b[k][n0];
            float a[8] = {t0.x, t0.y, t0.z, t0.w, t1.x, t1.y, t1.z, t1.w};
            float bb[4] = {t2.x, t2.y, t2.z, t2.w};
#pragma unroll
            for (int i = 0; i < 8; i++)
#pragma unroll
                for (int j = 0; j < 4; j++) acc[i][j] += a[i] * bb[j];
        }
    }
#pragma unroll
    for (int i = 0; i < 8; i++)
#pragma unroll
        for (int j = 0; j < 4; j++)
            g_part[ks][(m0 + i) * ND + bx * 128 + n0 + j] = acc[i][j];
}

// ---------------- reduce split-K partials into g_asum rows 0..63 (deterministic) ----
__global__ void kReduce() {
    int idx = blockIdx.x * blockDim.x + threadIdx.x;   // < 64*ND
    float s = 0.0f;
#pragma unroll
    for (int p = 0; p < SPLITK; p++) s += g_part[p][idx];
    g_asum[idx] = s;
}

// ---------------- extra centroid (rows with empty label; expected none) ------------
__global__ void kExtra(const float* __restrict__ x) {
    int d = blockIdx.x * blockDim.x + threadIdx.x;     // < ND
    int nz = g_nzero;
    float s = 0.0f;
    for (int j = 0; j < nz; j++) s += x[(size_t)g_zrows[j] * ND + d];
    g_asum[64 * ND + d] = s;
}

// ------ normalize anchors: anc = asum / max(||asum||, eps * max(cnt,1)) ------------
// Reference: anchor = asum/cnt; an = max(||asum||/cnt, eps);
// cos denom factor = cnt * an = max(||asum||, eps*cnt)  -> identical.
__global__ __launch_bounds__(256) void kNormAnc() {
    int c = blockIdx.x;   // 0..64
    __shared__ float red[256];
    __shared__ float s_scale;
    const float* row = &g_asum[c * ND];
    float s = 0.0f;
    for (int d = threadIdx.x; d < ND; d += 256) { float v = row[d]; s += v * v; }
    red[threadIdx.x] = s;
    __syncthreads();
    for (int o = 128; o > 0; o >>= 1) {
        if (threadIdx.x < o) red[threadIdx.x] += red[threadIdx.x + o];
        __syncthreads();
    }
    if (threadIdx.x == 0) {
        int cnt = (c < 64) ? g_counts[c] : g_nzero;
        float cf = (float)(cnt > 1 ? cnt : 1);
        s_scale = 1.0f / fmaxf(sqrtf(red[0]), EPSV * cf);
    }
    __syncthreads();
    float sc = s_scale;
    for (int d = threadIdx.x; d < ND; d += 256) g_anc[c * ND + d] = row[d] * sc;
}

// ---------------- row norms + dot with extra centroid (warp per row) ---------------
__global__ __launch_bounds__(256) void kNormDot(const float* __restrict__ x) {
    int row  = (blockIdx.x * blockDim.x + threadIdx.x) >> 5;
    int lane = threadIdx.x & 31;
    const float* xr  = &x[(size_t)row * ND];
    const float* a64 = &g_anc[64 * ND];
    float ss = 0.0f, dd = 0.0f;
#pragma unroll
    for (int p = 0; p < 8; p++) {
        int d = (lane + p * 32) * 4;
        float4 v = *(const float4*)&xr[d];
        float4 a = *(const float4*)&a64[d];
        ss += v.x * v.x + v.y * v.y + v.z * v.z + v.w * v.w;
        dd += v.x * a.x + v.y * a.y + v.z * a.z + v.w * a.w;
    }
#pragma unroll
    for (int o = 16; o; o >>= 1) {
        ss += __shfl_xor_sync(0xffffffffu, ss, o);
        dd += __shfl_xor_sync(0xffffffffu, dd, o);
    }
    if (lane == 0) {
        g_invxn[row] = 1.0f / fmaxf(sqrtf(ss), EPSV);
        g_dots[(size_t)row * NC + 64] = dd;
    }
}

// ---------------- GEMM2: dots[64 rows x 64 c] = x @ ancT, K = 1024 -----------------
#define KT2 32
__global__ __launch_bounds__(256) void kGemm2(const float* __restrict__ x) {
    int rb  = blockIdx.x * 64;
    int tid = threadIdx.x;
    __shared__ float s_x[KT2][68];   // [k][row]
    __shared__ float s_a[KT2][68];   // [k][c]

    float acc[4][4];
#pragma unroll
    for (int i = 0; i < 4; i++)
#pragma unroll
        for (int j = 0; j < 4; j++) acc[i][j] = 0.0f;

    int i0 = (tid >> 4) * 4;   // row frag 0..60
    int c0 = (tid & 15) * 4;   // col frag 0..60

    for (int k0 = 0; k0 < ND; k0 += KT2) {
        __syncthreads();
#pragma unroll
        for (int p = 0; p < 2; p++) {
            int idx = tid + p * 256;       // 0..511 : 64 rows x 8 float4
            int r  = idx >> 3;
            int kq = (idx & 7) << 2;
            float4 v = *(const float4*)&x[(size_t)(rb + r) * ND + k0 + kq];
            s_x[kq + 0][r] = v.x; s_x[kq + 1][r] = v.y;
            s_x[kq + 2][r] = v.z; s_x[kq + 3][r] = v.w;
            float4 a = *(const float4*)&g_anc[(size_t)r * ND + k0 + kq];  // r doubles as c
            s_a[kq + 0][r] = a.x; s_a[kq + 1][r] = a.y;
            s_a[kq + 2][r] = a.z; s_a[kq + 3][r] = a.w;
        }
        __syncthreads();
#pragma unroll
        for (int k = 0; k < KT2; k++) {
            float4 av = *(const float4*)&s_x[k][i0];
            float4 bv = *(const float4*)&s_a[k][c0];
            float a[4] = {av.x, av.y, av.z, av.w};
            float b[4] = {bv.x, bv.y, bv.z, bv.w};
#pragma unroll
            for (int i = 0; i < 4; i++)
#pragma unroll
                for (int j = 0; j < 4; j++) acc[i][j] += a[i] * b[j];
        }
    }
#pragma unroll
    for (int i = 0; i < 4; i++)
#pragma unroll
        for (int j = 0; j < 4; j++)
            g_dots[(size_t)(rb + i0 + i) * NC + c0 + j] = acc[i][j];
}

// ---- loss: per-row lse + positive-pair sum; DETERMINISTIC per-block partials ------
__global__ __launch_bounds__(256) void kLoss(const float* __restrict__ wp,
                                             const float* __restrict__ bp) {
    __shared__ int s_act[NC];
    __shared__ double s_red[8];
    if (threadIdx.x < NC) {
        int cnt = (threadIdx.x < 64) ? g_counts[threadIdx.x] : g_nzero;
        s_act[threadIdx.x] = cnt > 0;
    }
    __syncthreads();

    int warp = threadIdx.x >> 5;
    int row  = blockIdx.x * 8 + warp;
    int lane = threadIdx.x & 31;
    float w = *wp, b = *bp;

    unsigned long long m = g_mask[row];
    float inv = g_invxn[row];
    const float* dr = &g_dots[(size_t)row * NC];

    float l0 = s_act[lane]      ? fmaf(w * dr[lane]      , inv, b) : -INFINITY;
    float l1 = s_act[lane + 32] ? fmaf(w * dr[lane + 32] , inv, b) : -INFINITY;
    float l2 = (lane == 0 && s_act[64]) ? fmaf(w * dr[64], inv, b) : -INFINITY;

    float mx = fmaxf(fmaxf(l0, l1), l2);
#pragma unroll
    for (int o = 16; o; o >>= 1) mx = fmaxf(mx, __shfl_xor_sync(0xffffffffu, mx, o));

    float se = expf(l0 - mx) + expf(l1 - mx) + expf(l2 - mx);
#pragma unroll
    for (int o = 16; o; o >>= 1) se += __shfl_xor_sync(0xffffffffu, se, o);
    float lse = mx + logf(se);

    float ps = 0.0f;
    if ((m >> lane) & 1ULL)        ps += l0;
    if ((m >> (lane + 32)) & 1ULL) ps += l1;
    if (lane == 0 && m == 0ULL)    ps += l2;
#pragma unroll
    for (int o = 16; o; o >>= 1) ps += __shfl_xor_sync(0xffffffffu, ps, o);

    if (lane == 0) {
        int npos = m ? __popcll(m) : 1;
        s_red[warp] = (double)npos * (double)lse - (double)ps;
    }
    __syncthreads();
    if (threadIdx.x == 0) {
        double s = 0.0;
#pragma unroll
        for (int i = 0; i < 8; i++) s += s_red[i];
        g_lpart[blockIdx.x] = s;
    }
}

// ---------------- finalize (single block, deterministic reduction) -----------------
__global__ __launch_bounds__(256) void kFinal(float* out) {
    __shared__ double red[256];
    double s = 0.0;
    for (int i = threadIdx.x; i < NLOSSBLK; i += 256) s += g_lpart[i];
    red[threadIdx.x] = s;
    __syncthreads();
    for (int o = 128; o > 0; o >>= 1) {
        if (threadIdx.x < o) red[threadIdx.x] += red[threadIdx.x + o];
        __syncthreads();
    }
    if (threadIdx.x == 0) {
        long long np = 0;
        for (int c = 0; c < 64; c++) np += g_counts[c];
        np += g_nzero;
        out[0] = (float)(red[0] / (double)np);
    }
}

// ---------------- launch ----------------
extern "C" void kernel_launch(void* const* d_in, const int* in_sizes, int n_in,
                              void* d_out, int out_size) {
    const float* x     = (const float*)d_in[0];
    const void*  label = d_in[1];
    const float* wp    = (const float*)d_in[2];
    const float* bp    = (const float*)d_in[3];
    float* out = (float*)d_out;

    kInit<<<(NC * ND + 255) / 256, 256>>>();
    kDetect<<<256, 256>>>((const int*)label);
    kMask<<<NB / 8, 256>>>(label);
    {
        dim3 g(ND / 128, SPLITK);
        kGemm1<<<g, 256>>>(x);
    }
    kReduce<<<(64 * ND) / 256, 256>>>();
    kExtra<<<ND / 256, 256>>>(x);
    kNormAnc<<<NC, 256>>>();
    kNormDot<<<NB / 8, 256>>>(x);
    kGemm2<<<NB / 64, 256>>>(x);
    kLoss<<<NLOSSBLK, 256>>>(wp, bp);
    kFinal<<<1, 256>>>(out);
}

// round 6
// speedup vs baseline: 1.3808x; 1.3808x over previous
#include <cuda_runtime.h>
#include <math.h>
#include <stdint.h>

#define NB 16384      // batch rows
#define ND 1024       // feature dim
#define NC 65         // centroids incl. extra (dots stride)
#define NC2 72        // padded anchor rows for mma (65..71 zero)
#define EPSV 1e-8f
#define SPLITK 32
#define KCHUNK (NB / SPLITK)   // 512
#define NLOSSBLK (NB / 8)

// ---------------- scratch ----------------
__device__ unsigned long long g_mask[NB];
__device__ int    g_counts[64];
__device__ int    g_nzero;
__device__ int    g_odd;
__device__ int    g_zrows[NB];
__device__ float  g_part[SPLITK][64 * ND];
__device__ float  g_asum[NC * ND];
__device__ float  g_anc[NC2 * ND];
__device__ float  g_invxn[NB];
__device__ float  g_dots[(size_t)NB * NC];
__device__ double g_lpart[NLOSSBLK];

// ---------------- mma helpers ----------------
__device__ __forceinline__ uint32_t f2tf(float f) {
    uint32_t u; asm("cvt.rna.tf32.f32 %0, %1;" : "=r"(u) : "f"(f)); return u;
}
__device__ __forceinline__ void mma_tf32(float* d, uint32_t a0, uint32_t a1,
                                         uint32_t a2, uint32_t a3,
                                         uint32_t b0, uint32_t b1) {
    asm volatile(
        "mma.sync.aligned.m16n8k8.row.col.f32.tf32.tf32.f32 "
        "{%0,%1,%2,%3},{%4,%5,%6,%7},{%8,%9},{%0,%1,%2,%3};"
        : "+f"(d[0]), "+f"(d[1]), "+f"(d[2]), "+f"(d[3])
        : "r"(a0), "r"(a1), "r"(a2), "r"(a3), "r"(b0), "r"(b1));
}

// ---------------- init ----------------
__global__ void kInit() {
    int idx = blockIdx.x * blockDim.x + threadIdx.x;
    if (idx < 64) g_counts[idx] = 0;
    if (idx == 0) { g_nzero = 0; g_odd = 0; }
}

// ---------------- label width detection (int64 vs int32) ----------------
__global__ void kDetect(const int* lab32) {
    int found = 0;
    for (int idx = blockIdx.x * blockDim.x + threadIdx.x; idx < (NB * 64 / 2);
         idx += gridDim.x * blockDim.x) {
        if (lab32[2 * idx + 1] != 0) found = 1;
    }
    if (__syncthreads_or(found)) {
        if (threadIdx.x == 0) atomicOr(&g_odd, 1);
    }
}

// ---------------- masks + counts (warp per row) ----------------
__global__ __launch_bounds__(256) void kMask(const void* label) {
    __shared__ int s_cnt[64];
    if (threadIdx.x < 64) s_cnt[threadIdx.x] = 0;
    __syncthreads();

    int row  = (blockIdx.x * blockDim.x + threadIdx.x) >> 5;
    int lane = threadIdx.x & 31;
    bool is64 = (g_odd == 0);

    long long v0, v1;
    if (is64) {
        const long long* p = (const long long*)label;
        v0 = p[(size_t)row * 64 + lane];
        v1 = p[(size_t)row * 64 + 32 + lane];
    } else {
        const int* p = (const int*)label;
        v0 = p[(size_t)row * 64 + lane];
        v1 = p[(size_t)row * 64 + 32 + lane];
    }
    unsigned lo = __ballot_sync(0xffffffffu, v0 != 0);
    unsigned hi = __ballot_sync(0xffffffffu, v1 != 0);
    unsigned long long m = (unsigned long long)lo | ((unsigned long long)hi << 32);

    if (lane == 0) {
        g_mask[row] = m;
        if (m == 0ULL) {
            int p = atomicAdd(&g_nzero, 1);
            g_zrows[p] = row;
        }
    }
    if ((lo >> lane) & 1u) atomicAdd(&s_cnt[lane], 1);
    if ((hi >> lane) & 1u) atomicAdd(&s_cnt[lane + 32], 1);
    __syncthreads();
    if (threadIdx.x < 64) atomicAdd(&g_counts[threadIdx.x], s_cnt[threadIdx.x]);
}

// ======== GEMM1 (tensor core tf32): part[ks] = labT(64 x 512) @ x(512 x 128cols) ====
// A (label bits) generated in registers from g_mask — exact in tf32.
__global__ __launch_bounds__(256) void kGemm1(const float* __restrict__ x) {
    int bx  = blockIdx.x;          // 0..7  : 128-col tile
    int ks  = blockIdx.y;          // 0..31 : K slice
    int tid = threadIdx.x;
    int warp = tid >> 5, lane = tid & 31;
    int mw = warp & 3;             // m-warp: m base mw*16
    int nw = warp >> 2;            // n-warp: n base nw*64
    int gid = lane >> 2, tig = lane & 3;

    __shared__ uint32_t s_b[32][136];          // tf32 x tile [k][n], pad 136
    __shared__ unsigned long long s_m[32];

    float acc[8][4];
#pragma unroll
    for (int j = 0; j < 8; j++)
#pragma unroll
        for (int q = 0; q < 4; q++) acc[j][q] = 0.0f;

    int kbase = ks * KCHUNK;
    for (int t = 0; t < KCHUNK / 32; t++) {
        int k0 = kbase + t * 32;
        __syncthreads();
#pragma unroll
        for (int p = 0; p < 4; p++) {
            int idx = tid + p * 256;
            int kr = idx >> 5;
            int nc = (idx & 31) << 2;
            float4 v = *(const float4*)&x[(size_t)(k0 + kr) * ND + bx * 128 + nc];
            uint4 u = make_uint4(f2tf(v.x), f2tf(v.y), f2tf(v.z), f2tf(v.w));
            *(uint4*)&s_b[kr][nc] = u;
        }
        if (tid < 32) s_m[tid] = g_mask[k0 + tid];
        __syncthreads();
#pragma unroll
        for (int kk = 0; kk < 4; kk++) {
            unsigned long long mlo = s_m[kk * 8 + tig];
            unsigned long long mhi = s_m[kk * 8 + tig + 4];
            int mb = mw * 16 + gid;
            uint32_t a0 = ((mlo >> mb)        & 1ULL) ? 0x3F800000u : 0u;
            uint32_t a1 = ((mlo >> (mb + 8))  & 1ULL) ? 0x3F800000u : 0u;
            uint32_t a2 = ((mhi >> mb)        & 1ULL) ? 0x3F800000u : 0u;
            uint32_t a3 = ((mhi >> (mb + 8))  & 1ULL) ? 0x3F800000u : 0u;
#pragma unroll
            for (int j = 0; j < 8; j++) {
                uint32_t b0 = s_b[kk * 8 + tig][nw * 64 + j * 8 + gid];
                uint32_t b1 = s_b[kk * 8 + tig + 4][nw * 64 + j * 8 + gid];
                mma_tf32(acc[j], a0, a1, a2, a3, b0, b1);
            }
        }
    }
    // epilogue: C[m][n] frag mapping -> partials
    int mg = mw * 16 + gid;
#pragma unroll
    for (int j = 0; j < 8; j++) {
        int n = bx * 128 + nw * 64 + j * 8 + tig * 2;
        g_part[ks][mg * ND + n]           = acc[j][0];
        g_part[ks][mg * ND + n + 1]       = acc[j][1];
        g_part[ks][(mg + 8) * ND + n]     = acc[j][2];
        g_part[ks][(mg + 8) * ND + n + 1] = acc[j][3];
    }
}

// ---------------- reduce split-K partials (deterministic) ----------------
__global__ void kReduce() {
    int idx = blockIdx.x * blockDim.x + threadIdx.x;
    float s = 0.0f;
#pragma unroll
    for (int p = 0; p < SPLITK; p++) s += g_part[p][idx];
    g_asum[idx] = s;
}

// ---------------- extra centroid (rows with empty label) ----------------
__global__ void kExtra(const float* __restrict__ x) {
    int d = blockIdx.x * blockDim.x + threadIdx.x;
    int nz = g_nzero;
    float s = 0.0f;
    for (int j = 0; j < nz; j++) s += x[(size_t)g_zrows[j] * ND + d];
    g_asum[64 * ND + d] = s;
}

// ---- anchors: anc = asum / max(||asum||, eps*max(cnt,1)); rows 65..71 = 0 ----
__global__ __launch_bounds__(256) void kNormAnc() {
    int c = blockIdx.x;   // 0..71
    if (c >= NC) {
        for (int d = threadIdx.x; d < ND; d += 256) g_anc[c * ND + d] = 0.0f;
        return;
    }
    __shared__ float red[256];
    __shared__ float s_scale;
    const float* row = &g_asum[c * ND];
    float s = 0.0f;
    for (int d = threadIdx.x; d < ND; d += 256) { float v = row[d]; s += v * v; }
    red[threadIdx.x] = s;
    __syncthreads();
    for (int o = 128; o > 0; o >>= 1) {
        if (threadIdx.x < o) red[threadIdx.x] += red[threadIdx.x + o];
        __syncthreads();
    }
    if (threadIdx.x == 0) {
        int cnt = (c < 64) ? g_counts[c] : g_nzero;
        float cf = (float)(cnt > 1 ? cnt : 1);
        s_scale = 1.0f / fmaxf(sqrtf(red[0]), EPSV * cf);
    }
    __syncthreads();
    float sc = s_scale;
    for (int d = threadIdx.x; d < ND; d += 256) g_anc[c * ND + d] = row[d] * sc;
}

// ======== GEMM2 (tensor core tf32): dots[128 rows x 65] = x @ ancT, fused norms ====
__global__ __launch_bounds__(256) void kGemm2(const float* __restrict__ x) {
    int rb  = blockIdx.x * 128;
    int tid = threadIdx.x;
    int warp = tid >> 5, lane = tid & 31;
    int gid = lane >> 2, tig = lane & 3;

    __shared__ uint32_t s_x[128][36];   // tf32 x tile [m][k], pad 36
    __shared__ uint32_t s_a[32][72];    // tf32 anchor tile [k][c]
    __shared__ float    s_nrm[128][8];

    float acc[9][4];
#pragma unroll
    for (int j = 0; j < 9; j++)
#pragma unroll
        for (int q = 0; q < 4; q++) acc[j][q] = 0.0f;
    float ss[4] = {0.0f, 0.0f, 0.0f, 0.0f};

    for (int k0 = 0; k0 < ND; k0 += 32) {
        __syncthreads();
#pragma unroll
        for (int p = 0; p < 4; p++) {
            int idx = tid + p * 256;
            int r  = idx >> 3;
            int kq = (idx & 7) << 2;
            float4 v = *(const float4*)&x[(size_t)(rb + r) * ND + k0 + kq];
            ss[p] += v.x * v.x + v.y * v.y + v.z * v.z + v.w * v.w;
            uint4 u = make_uint4(f2tf(v.x), f2tf(v.y), f2tf(v.z), f2tf(v.w));
            *(uint4*)&s_x[r][kq] = u;
        }
        // anchors: 72 rows x 8 float4 = 576 float4, transpose into s_a[k][c]
#pragma unroll
        for (int p = 0; p < 3; p++) {
            int idx = tid + p * 256;
            if (idx < 576) {
                int c  = idx >> 3;
                int kq = (idx & 7) << 2;
                float4 v = *(const float4*)&g_anc[(size_t)c * ND + k0 + kq];
                s_a[kq + 0][c] = f2tf(v.x);
                s_a[kq + 1][c] = f2tf(v.y);
                s_a[kq + 2][c] = f2tf(v.z);
                s_a[kq + 3][c] = f2tf(v.w);
            }
        }
        __syncthreads();
#pragma unroll
        for (int kk = 0; kk < 4; kk++) {
            int mB = warp * 16 + gid;
            uint32_t a0 = s_x[mB][kk * 8 + tig];
            uint32_t a1 = s_x[mB + 8][kk * 8 + tig];
            uint32_t a2 = s_x[mB][kk * 8 + tig + 4];
            uint32_t a3 = s_x[mB + 8][kk * 8 + tig + 4];
#pragma unroll
            for (int j = 0; j < 9; j++) {
                uint32_t b0 = s_a[kk * 8 + tig][j * 8 + gid];
                uint32_t b1 = s_a[kk * 8 + tig + 4][j * 8 + gid];
                mma_tf32(acc[j], a0, a1, a2, a3, b0, b1);
            }
        }
    }
    // fused row norms (deterministic): 8 partials per row
    __syncthreads();
#pragma unroll
    for (int p = 0; p < 4; p++) s_nrm[(tid >> 3) + p * 32][tid & 7] = ss[p];
    __syncthreads();
    if (tid < 128) {
        float s = 0.0f;
#pragma unroll
        for (int q = 0; q < 8; q++) s += s_nrm[tid][q];
        g_invxn[rb + tid] = 1.0f / fmaxf(sqrtf(s), EPSV);
    }
    // epilogue: dots (only cols < 65)
    int mg = rb + warp * 16 + gid;
#pragma unroll
    for (int j = 0; j < 9; j++) {
        int n = j * 8 + tig * 2;
        if (n < NC) {
            g_dots[(size_t)mg * NC + n]       = acc[j][0];
            g_dots[(size_t)(mg + 8) * NC + n] = acc[j][2];
        }
        if (n + 1 < NC) {
            g_dots[(size_t)mg * NC + n + 1]       = acc[j][1];
            g_dots[(size_t)(mg + 8) * NC + n + 1] = acc[j][3];
        }
    }
}

// ---- loss: per-row lse + positive-pair sum; deterministic partials ----
__global__ __launch_bounds__(256) void kLoss(const float* __restrict__ wp,
                                             const float* __restrict__ bp) {
    __shared__ int s_act[NC];
    __shared__ double s_red[8];
    if (threadIdx.x < NC) {
        int cnt = (threadIdx.x < 64) ? g_counts[threadIdx.x] : g_nzero;
        s_act[threadIdx.x] = cnt > 0;
    }
    __syncthreads();

    int warp = threadIdx.x >> 5;
    int row  = blockIdx.x * 8 + warp;
    int lane = threadIdx.x & 31;
    float w = *wp, b = *bp;

    unsigned long long m = g_mask[row];
    float inv = g_invxn[row];
    const float* dr = &g_dots[(size_t)row * NC];

    float l0 = s_act[lane]      ? fmaf(w * dr[lane]      , inv, b) : -INFINITY;
    float l1 = s_act[lane + 32] ? fmaf(w * dr[lane + 32] , inv, b) : -INFINITY;
    float l2 = (lane == 0 && s_act[64]) ? fmaf(w * dr[64], inv, b) : -INFINITY;

    float mx = fmaxf(fmaxf(l0, l1), l2);
#pragma unroll
    for (int o = 16; o; o >>= 1) mx = fmaxf(mx, __shfl_xor_sync(0xffffffffu, mx, o));

    float se = expf(l0 - mx) + expf(l1 - mx) + expf(l2 - mx);
#pragma unroll
    for (int o = 16; o; o >>= 1) se += __shfl_xor_sync(0xffffffffu, se, o);
    float lse = mx + logf(se);

    float ps = 0.0f;
    if ((m >> lane) & 1ULL)        ps += l0;
    if ((m >> (lane + 32)) & 1ULL) ps += l1;
    if (lane == 0 && m == 0ULL)    ps += l2;
#pragma unroll
    for (int o = 16; o; o >>= 1) ps += __shfl_xor_sync(0xffffffffu, ps, o);

    if (lane == 0) {
        int npos = m ? __popcll(m) : 1;
        s_red[warp] = (double)npos * (double)lse - (double)ps;
    }
    __syncthreads();
    if (threadIdx.x == 0) {
        double s = 0.0;
#pragma unroll
        for (int i = 0; i < 8; i++) s += s_red[i];
        g_lpart[blockIdx.x] = s;
    }
}

// ---------------- finalize ----------------
__global__ __launch_bounds__(256) void kFinal(float* out) {
    __shared__ double red[256];
    double s = 0.0;
    for (int i = threadIdx.x; i < NLOSSBLK; i += 256) s += g_lpart[i];
    red[threadIdx.x] = s;
    __syncthreads();
    for (int o = 128; o > 0; o >>= 1) {
        if (threadIdx.x < o) red[threadIdx.x] += red[threadIdx.x + o];
        __syncthreads();
    }
    if (threadIdx.x == 0) {
        long long np = 0;
        for (int c = 0; c < 64; c++) np += g_counts[c];
        np += g_nzero;
        out[0] = (float)(red[0] / (double)np);
    }
}

// ---------------- launch ----------------
extern "C" void kernel_launch(void* const* d_in, const int* in_sizes, int n_in,
                              void* d_out, int out_size) {
    const float* x     = (const float*)d_in[0];
    const void*  label = d_in[1];
    const float* wp    = (const float*)d_in[2];
    const float* bp    = (const float*)d_in[3];
    float* out = (float*)d_out;

    kInit<<<1, 256>>>();
    kDetect<<<256, 256>>>((const int*)label);
    kMask<<<NB / 8, 256>>>(label);
    {
        dim3 g(ND / 128, SPLITK);
        kGemm1<<<g, 256>>>(x);
    }
    kReduce<<<(64 * ND) / 256, 256>>>();
    kExtra<<<ND / 256, 256>>>(x);
    kNormAnc<<<NC2, 256>>>();
    kGemm2<<<NB / 128, 256>>>(x);
    kLoss<<<NLOSSBLK, 256>>>(wp, bp);
    kFinal<<<1, 256>>>(out);
}